// round 13
// baseline (speedup 1.0000x reference)
#include <cuda_runtime.h>
#include <cuda_fp16.h>
#include <math.h>

// DistributionLoss: local 7x7x3 std of two [16,3,512,512] f32 tensors,
// smooth-L1 between std maps, global mean.
//
// R13: amortization II. 64x64 tile with 512-thread blocks at
// launch_bounds(512,3): same 48 warps/SM and same 2.31-generation schedule
// as R12, but barriers/output halved and halo traffic/output -8%.
// Tree sums, 16B paired in-place hsum, fp16 cells, RSQ sqrt.

#define TW    64
#define TH    64
#define HALO  3
#define HR    70                  // halo rows  (TH + 6)
#define WC    70                  // halo cols  (TW + 6)
#define PITCH 78                  // smem pitch in 8B cells (even; max addr 77)
#define NTHR  512
#define NINV  (1.0f / 147.0f)
#define EPS   1e-8f
#define HWSZ  (512 * 512)
#define NPIX  (16.0f * 512.0f * 512.0f)
#define NBLK  1024                // 8 x 8 x 16

// Pair-granular swizzle (pairs = 16B units): distinct mod 8 for stride-2.
#define SWP(p) ((p) + ((p) >> 3))
__device__ __forceinline__ int cellAddr(int c) {
    int p = c >> 1;
    return 2 * SWP(p) + (c & 1);
}

__device__ float        g_partials[NBLK];
__device__ unsigned int g_count;   // zero-init; self-resets via atomicInc wrap

struct Cell { __half2 p, t; };     // (s, s2) for pred / tgt

__device__ __forceinline__ Cell mk(unsigned int a, unsigned int b) {
    Cell c;
    c.p = *reinterpret_cast<__half2*>(&a);
    c.t = *reinterpret_cast<__half2*>(&b);
    return c;
}
__device__ __forceinline__ uint2 c2u(Cell c) {
    uint2 v;
    v.x = *reinterpret_cast<unsigned int*>(&c.p);
    v.y = *reinterpret_cast<unsigned int*>(&c.t);
    return v;
}
__device__ __forceinline__ Cell u2c(uint2 v) { return mk(v.x, v.y); }
__device__ __forceinline__ Cell lo4(uint4 u) { return mk(u.x, u.y); }
__device__ __forceinline__ Cell hi4(uint4 u) { return mk(u.z, u.w); }
__device__ __forceinline__ Cell cadd(Cell a, Cell b) {
    Cell r; r.p = __hadd2(a.p, b.p); r.t = __hadd2(a.t, b.t); return r;
}
// fast sqrt: x * rsqrt(x), x > 0 guaranteed (x >= EPS)
__device__ __forceinline__ float fsqrt_fast(float x) { return x * rsqrtf(x); }

// Tree 7-sums over a 10-window: w_j = sum(v[j..j+6]), j=0..3. Depth ~4.
__device__ __forceinline__ void tree7(const Cell v[10], Cell w[4]) {
    Cell p0 = cadd(v[0], v[1]);
    Cell p2 = cadd(v[2], v[3]);
    Cell p4 = cadd(v[4], v[5]);
    Cell p6 = cadd(v[6], v[7]);
    Cell p8 = cadd(v[8], v[9]);
    Cell t  = cadd(p2, p4);      // v2..v5
    Cell s1 = cadd(t, p6);       // v2..v7
    Cell r  = cadd(p6, p8);      // v6..v9
    w[0] = cadd(cadd(p0, t), v[6]);
    w[1] = cadd(v[1], s1);
    w[2] = cadd(s1, v[8]);
    w[3] = cadd(cadd(v[3], p4), r);
}

__global__ __launch_bounds__(NTHR, 3)
void dist_loss_main(const float* __restrict__ pred,
                    const float* __restrict__ tgt,
                    float* __restrict__ out)
{
    __shared__ __align__(16) uint2 s_raw[HR * PITCH];  // cells; hsums in-place
    __shared__ float s_warp[16];
    __shared__ bool  s_is_last;

    const int tid  = threadIdx.y * 32 + threadIdx.x;
    const int lane = threadIdx.x;
    const int wid  = threadIdx.y;
    const int x0   = blockIdx.x * TW;
    const int y0   = blockIdx.y * TH;

    const float* p  = pred + (size_t)blockIdx.z * 3 * HWSZ;
    const float* tg = tgt  + (size_t)blockIdx.z * 3 * HWSZ;

    // ---- Phase 1: 1260 tasks = 70 rows x 18 float4 col-groups ----
    for (int task = tid; task < HR * 18; task += NTHR) {
        int r   = task / 18;
        int g   = task - r * 18;
        int gy  = y0 - HALO + r;
        int gx0 = x0 - 4 + 4 * g;
        bool rowok = ((unsigned)gy < 512u);

        __half2 hp[4], ht[4];
        if (rowok && gx0 >= 0 && gx0 <= 508) {
            size_t off = (size_t)gy * 512 + gx0;
            float4 a0 = *(const float4*)(p + off);
            float4 a1 = *(const float4*)(p + HWSZ + off);
            float4 a2 = *(const float4*)(p + 2 * HWSZ + off);
            float4 b0 = *(const float4*)(tg + off);
            float4 b1 = *(const float4*)(tg + HWSZ + off);
            float4 b2 = *(const float4*)(tg + 2 * HWSZ + off);
            hp[0] = __floats2half2_rn(a0.x + a1.x + a2.x, a0.x*a0.x + a1.x*a1.x + a2.x*a2.x);
            hp[1] = __floats2half2_rn(a0.y + a1.y + a2.y, a0.y*a0.y + a1.y*a1.y + a2.y*a2.y);
            hp[2] = __floats2half2_rn(a0.z + a1.z + a2.z, a0.z*a0.z + a1.z*a1.z + a2.z*a2.z);
            hp[3] = __floats2half2_rn(a0.w + a1.w + a2.w, a0.w*a0.w + a1.w*a1.w + a2.w*a2.w);
            ht[0] = __floats2half2_rn(b0.x + b1.x + b2.x, b0.x*b0.x + b1.x*b1.x + b2.x*b2.x);
            ht[1] = __floats2half2_rn(b0.y + b1.y + b2.y, b0.y*b0.y + b1.y*b1.y + b2.y*b2.y);
            ht[2] = __floats2half2_rn(b0.z + b1.z + b2.z, b0.z*b0.z + b1.z*b1.z + b2.z*b2.z);
            ht[3] = __floats2half2_rn(b0.w + b1.w + b2.w, b0.w*b0.w + b1.w*b1.w + b2.w*b2.w);
        } else {
#pragma unroll
            for (int j = 0; j < 4; j++) {
                int gx = gx0 + j;
                float v0 = 0.f, v1 = 0.f, v2 = 0.f;
                float w0 = 0.f, w1 = 0.f, w2 = 0.f;
                if (rowok && ((unsigned)gx < 512u)) {
                    size_t off = (size_t)gy * 512 + gx;
                    v0 = p[off];  v1 = p[HWSZ + off];  v2 = p[2 * HWSZ + off];
                    w0 = tg[off]; w1 = tg[HWSZ + off]; w2 = tg[2 * HWSZ + off];
                }
                hp[j] = __floats2half2_rn(v0 + v1 + v2, v0*v0 + v1*v1 + v2*v2);
                ht[j] = __floats2half2_rn(w0 + w1 + w2, w0*w0 + w1*w1 + w2*w2);
            }
        }
#pragma unroll
        for (int j = 0; j < 4; j++) {
            int c = 4 * g + j - 1;
            if ((unsigned)c < (unsigned)WC) {
                Cell cl; cl.p = hp[j]; cl.t = ht[j];
                s_raw[r * PITCH + cellAddr(c)] = c2u(cl);
            }
        }
    }
    __syncthreads();                                           // B1

    // ---- Phase 2: horizontal 7-sum IN PLACE, 16B paired, tree sums ----
    // 70 rows x 16 groups; passes handle rows 0-31 / 32-63 / 64-69.
    // Row-disjoint passes: only the load->store barrier within each pass.
    {
        const int g2 = tid & 15;
        const int r2 = tid >> 4;     // 0..31
        int pa[5];
#pragma unroll
        for (int i = 0; i < 5; i++) pa[i] = SWP(2 * g2 + i);   // uint4 units

#pragma unroll
        for (int pss = 0; pss < 3; pss++) {
            int r = pss * 32 + r2;
            bool active = (r < HR);
            uint4 st0, st1;
            if (active) {
                uint4* rp4 = (uint4*)(s_raw + r * PITCH);
                uint4 u0 = rp4[pa[0]];
                uint4 u1 = rp4[pa[1]];
                uint4 u2 = rp4[pa[2]];
                uint4 u3 = rp4[pa[3]];
                uint4 u4v = rp4[pa[4]];
                Cell v[10] = { lo4(u0), hi4(u0), lo4(u1), hi4(u1), lo4(u2),
                               hi4(u2), lo4(u3), hi4(u3), lo4(u4v), hi4(u4v) };
                Cell w[4];
                tree7(v, w);
                uint2 h0 = c2u(w[0]), h1 = c2u(w[1]);
                uint2 h2 = c2u(w[2]), h3 = c2u(w[3]);
                st0 = make_uint4(h0.x, h0.y, h1.x, h1.y);
                st1 = make_uint4(h2.x, h2.y, h3.x, h3.y);
            }
            __syncthreads();                                   // B2/B3/B4
            if (active) {
                uint4* rp4 = (uint4*)(s_raw + r * PITCH);
                rp4[pa[0]] = st0;
                rp4[pa[1]] = st1;
            }
        }
    }
    __syncthreads();                                           // B5

    // ---- Phase 3: vertical tree 7-sums, rolling window, 8 rows/thread ----
    float acc = 0.f;
    {
        const int c3 = tid & 63;     // output col 0..63
        const int rg = tid >> 6;     // 0..7 -> output rows 8rg..8rg+7
        const uint2* col = s_raw + cellAddr(c3);
        const int rb = rg * 8;

        Cell v[10];
#pragma unroll
        for (int i = 0; i < 10; i++)
            v[i] = u2c(col[(rb + i) * PITCH]);

#pragma unroll
        for (int half = 0; half < 2; half++) {
            Cell w[4];
            tree7(v, w);
#pragma unroll
            for (int q = 0; q < 4; q++) {
                float2 fp = __half22float2(w[q].p);   // (S, S2) pred
                float2 ft = __half22float2(w[q].t);   // (S, S2) tgt
                float mup  = fp.x * NINV;
                float varp = fp.y * NINV - mup * mup;
                float sdp  = fsqrt_fast(varp + EPS);
                float mut  = ft.x * NINV;
                float vart = ft.y * NINV - mut * mut;
                float sdt  = fsqrt_fast(vart + EPS);
                float d  = sdp - sdt;
                float ad = fabsf(d);
                acc += (ad < 1.0f) ? 0.5f * d * d : (ad - 0.5f);
            }
            if (half == 0) {
                // shift window down by 4 rows: rows rb+4..rb+13
#pragma unroll
                for (int i = 0; i < 6; i++) v[i] = v[i + 4];
#pragma unroll
                for (int i = 6; i < 10; i++)
                    v[i] = u2c(col[(rb + 4 + i) * PITCH]);
            }
        }
    }

    // ---- block reduction: warp shuffle + one barrier ----
#pragma unroll
    for (int off = 16; off > 0; off >>= 1)
        acc += __shfl_down_sync(0xffffffffu, acc, off);
    if (lane == 0) s_warp[wid] = acc;
    __syncthreads();                                           // B6

    const int pidx = blockIdx.z * 64 + blockIdx.y * 8 + blockIdx.x;
    if (wid == 0) {
        float a = (lane < 16) ? s_warp[lane] : 0.f;
#pragma unroll
        for (int off = 8; off > 0; off >>= 1)
            a += __shfl_down_sync(0xffffffffu, a, off);
        if (lane == 0) {
            g_partials[pidx] = a;
            __threadfence();
            unsigned int prev = atomicInc(&g_count, NBLK - 1);  // wraps to 0
            s_is_last = (prev == NBLK - 1);
        }
    }
    __syncthreads();                                           // B7

    // ---- last block: final deterministic reduction ----
    if (s_is_last) {
        float a = g_partials[tid] + g_partials[tid + NTHR];
#pragma unroll
        for (int off = 16; off > 0; off >>= 1)
            a += __shfl_down_sync(0xffffffffu, a, off);
        if (lane == 0) s_warp[wid] = a;
        __syncthreads();
        if (tid == 0) {
            float s = 0.f;
#pragma unroll
            for (int i = 0; i < 16; i++) s += s_warp[i];
            out[0] = s * (1.0f / NPIX);
        }
    }
}

extern "C" void kernel_launch(void* const* d_in, const int* in_sizes, int n_in,
                              void* d_out, int out_size)
{
    const float* pred = (const float*)d_in[0];
    const float* tgt  = (const float*)d_in[1];
    float* out = (float*)d_out;

    dim3 grid(8, 8, 16);    // x tiles (64 wide), y tiles (64 tall), batch
    dim3 block(32, 16);
    dist_loss_main<<<grid, block>>>(pred, tgt, out);
}

// round 14
// speedup vs baseline: 1.0605x; 1.0605x over previous
#include <cuda_runtime.h>
#include <cuda_fp16.h>
#include <math.h>

// DistributionLoss: local 7x7x3 std of two [16,3,512,512] f32 tensors,
// smooth-L1 between std maps, global mean.
//
// R14: R12 base (64x32 tile, 256 thr, fp16 cells, tree sums, 16B paired
// in-place hsum, RSQ) with phase 2 made WARP-LOCAL: each warp owns whole
// rows (16 lanes x 2 rows), so the in-place load->store hazard needs only
// __syncwarp. Block barriers: 7 -> 4.

#define TW    64
#define TH    32
#define HALO  3
#define HR    38                  // halo rows  (TH + 6)
#define WC    70                  // halo cols  (TW + 6)
#define PITCH 78                  // smem pitch in 8B cells (even; max addr 77)
#define NINV  (1.0f / 147.0f)
#define EPS   1e-8f
#define HWSZ  (512 * 512)
#define NPIX  (16.0f * 512.0f * 512.0f)
#define NBLK  2048                // 8 x 16 x 16

// Pair-granular swizzle (pairs = 16B units): distinct mod 8 for stride-2.
#define SWP(p) ((p) + ((p) >> 3))
__device__ __forceinline__ int cellAddr(int c) {
    int p = c >> 1;
    return 2 * SWP(p) + (c & 1);
}

__device__ float        g_partials[NBLK];
__device__ unsigned int g_count;   // zero-init; self-resets via atomicInc wrap

struct Cell { __half2 p, t; };     // (s, s2) for pred / tgt

__device__ __forceinline__ Cell mk(unsigned int a, unsigned int b) {
    Cell c;
    c.p = *reinterpret_cast<__half2*>(&a);
    c.t = *reinterpret_cast<__half2*>(&b);
    return c;
}
__device__ __forceinline__ uint2 c2u(Cell c) {
    uint2 v;
    v.x = *reinterpret_cast<unsigned int*>(&c.p);
    v.y = *reinterpret_cast<unsigned int*>(&c.t);
    return v;
}
__device__ __forceinline__ Cell u2c(uint2 v) { return mk(v.x, v.y); }
__device__ __forceinline__ Cell lo4(uint4 u) { return mk(u.x, u.y); }
__device__ __forceinline__ Cell hi4(uint4 u) { return mk(u.z, u.w); }
__device__ __forceinline__ Cell cadd(Cell a, Cell b) {
    Cell r; r.p = __hadd2(a.p, b.p); r.t = __hadd2(a.t, b.t); return r;
}
// fast sqrt: x * rsqrt(x), x > 0 guaranteed (x >= EPS)
__device__ __forceinline__ float fsqrt_fast(float x) { return x * rsqrtf(x); }

// Tree 7-sums over a 10-window: w_j = sum(v[j..j+6]), j=0..3. Depth ~4.
__device__ __forceinline__ void tree7(const Cell v[10], Cell w[4]) {
    Cell p0 = cadd(v[0], v[1]);
    Cell p2 = cadd(v[2], v[3]);
    Cell p4 = cadd(v[4], v[5]);
    Cell p6 = cadd(v[6], v[7]);
    Cell p8 = cadd(v[8], v[9]);
    Cell t  = cadd(p2, p4);      // v2..v5
    Cell s1 = cadd(t, p6);       // v2..v7
    Cell r  = cadd(p6, p8);      // v6..v9
    w[0] = cadd(cadd(p0, t), v[6]);
    w[1] = cadd(v[1], s1);
    w[2] = cadd(s1, v[8]);
    w[3] = cadd(cadd(v[3], p4), r);
}

__global__ __launch_bounds__(256, 6)
void dist_loss_main(const float* __restrict__ pred,
                    const float* __restrict__ tgt,
                    float* __restrict__ out)
{
    __shared__ __align__(16) uint2 s_raw[HR * PITCH];  // cells; hsums in-place
    __shared__ float s_warp[8];
    __shared__ bool  s_is_last;

    const int tid  = threadIdx.y * 32 + threadIdx.x;
    const int lane = threadIdx.x;
    const int wid  = threadIdx.y;
    const int x0   = blockIdx.x * TW;
    const int y0   = blockIdx.y * TH;

    const float* p  = pred + (size_t)blockIdx.z * 3 * HWSZ;
    const float* tg = tgt  + (size_t)blockIdx.z * 3 * HWSZ;

    // ---- Phase 1: 684 tasks = 38 rows x 18 float4 col-groups ----
    for (int task = tid; task < HR * 18; task += 256) {
        int r   = task / 18;
        int g   = task - r * 18;
        int gy  = y0 - HALO + r;
        int gx0 = x0 - 4 + 4 * g;
        bool rowok = ((unsigned)gy < 512u);

        __half2 hp[4], ht[4];
        if (rowok && gx0 >= 0 && gx0 <= 508) {
            size_t off = (size_t)gy * 512 + gx0;
            float4 a0 = *(const float4*)(p + off);
            float4 a1 = *(const float4*)(p + HWSZ + off);
            float4 a2 = *(const float4*)(p + 2 * HWSZ + off);
            float4 b0 = *(const float4*)(tg + off);
            float4 b1 = *(const float4*)(tg + HWSZ + off);
            float4 b2 = *(const float4*)(tg + 2 * HWSZ + off);
            hp[0] = __floats2half2_rn(a0.x + a1.x + a2.x, a0.x*a0.x + a1.x*a1.x + a2.x*a2.x);
            hp[1] = __floats2half2_rn(a0.y + a1.y + a2.y, a0.y*a0.y + a1.y*a1.y + a2.y*a2.y);
            hp[2] = __floats2half2_rn(a0.z + a1.z + a2.z, a0.z*a0.z + a1.z*a1.z + a2.z*a2.z);
            hp[3] = __floats2half2_rn(a0.w + a1.w + a2.w, a0.w*a0.w + a1.w*a1.w + a2.w*a2.w);
            ht[0] = __floats2half2_rn(b0.x + b1.x + b2.x, b0.x*b0.x + b1.x*b1.x + b2.x*b2.x);
            ht[1] = __floats2half2_rn(b0.y + b1.y + b2.y, b0.y*b0.y + b1.y*b1.y + b2.y*b2.y);
            ht[2] = __floats2half2_rn(b0.z + b1.z + b2.z, b0.z*b0.z + b1.z*b1.z + b2.z*b2.z);
            ht[3] = __floats2half2_rn(b0.w + b1.w + b2.w, b0.w*b0.w + b1.w*b1.w + b2.w*b2.w);
        } else {
#pragma unroll
            for (int j = 0; j < 4; j++) {
                int gx = gx0 + j;
                float v0 = 0.f, v1 = 0.f, v2 = 0.f;
                float w0 = 0.f, w1 = 0.f, w2 = 0.f;
                if (rowok && ((unsigned)gx < 512u)) {
                    size_t off = (size_t)gy * 512 + gx;
                    v0 = p[off];  v1 = p[HWSZ + off];  v2 = p[2 * HWSZ + off];
                    w0 = tg[off]; w1 = tg[HWSZ + off]; w2 = tg[2 * HWSZ + off];
                }
                hp[j] = __floats2half2_rn(v0 + v1 + v2, v0*v0 + v1*v1 + v2*v2);
                ht[j] = __floats2half2_rn(w0 + w1 + w2, w0*w0 + w1*w1 + w2*w2);
            }
        }
#pragma unroll
        for (int j = 0; j < 4; j++) {
            int c = 4 * g + j - 1;
            if ((unsigned)c < (unsigned)WC) {
                Cell cl; cl.p = hp[j]; cl.t = ht[j];
                s_raw[r * PITCH + cellAddr(c)] = c2u(cl);
            }
        }
    }
    __syncthreads();                                           // B1

    // ---- Phase 2: horizontal 7-sum IN PLACE, warp-local rows ----
    // Warp owns row-pairs (2 rows x 16 groups = 32 lanes). The load->store
    // hazard is warp-internal -> __syncwarp only, NO block barriers.
    // 19 row-pairs (rows 0..37) strided over 8 warps.
    {
        const int g2 = lane & 15;
        const int rp = lane >> 4;    // 0 or 1: row within pair
        int pa[5];
#pragma unroll
        for (int i = 0; i < 5; i++) pa[i] = SWP(2 * g2 + i);   // uint4 units

        for (int pairIdx = wid; pairIdx < 19; pairIdx += 8) {
            int r = 2 * pairIdx + rp;                          // 0..37 < HR
            uint4* rp4 = (uint4*)(s_raw + r * PITCH);
            uint4 u0 = rp4[pa[0]];
            uint4 u1 = rp4[pa[1]];
            uint4 u2 = rp4[pa[2]];
            uint4 u3 = rp4[pa[3]];
            uint4 u4v = rp4[pa[4]];
            Cell v[10] = { lo4(u0), hi4(u0), lo4(u1), hi4(u1), lo4(u2),
                           hi4(u2), lo4(u3), hi4(u3), lo4(u4v), hi4(u4v) };
            Cell w[4];
            tree7(v, w);
            uint2 h0 = c2u(w[0]), h1 = c2u(w[1]);
            uint2 h2 = c2u(w[2]), h3 = c2u(w[3]);
            __syncwarp();                                      // loads before stores
            rp4[pa[0]] = make_uint4(h0.x, h0.y, h1.x, h1.y);
            rp4[pa[1]] = make_uint4(h2.x, h2.y, h3.x, h3.y);
            __syncwarp();                                      // stores before next loads
        }
    }
    __syncthreads();                                           // B2

    // ---- Phase 3: vertical tree 7-sums, rolling window, 8 rows/thread ----
    float acc = 0.f;
    {
        const int c3 = tid & 63;     // output col 0..63
        const int rg = tid >> 6;     // 0..3 -> output rows 8rg..8rg+7
        const uint2* col = s_raw + cellAddr(c3);
        const int rb = rg * 8;

        Cell v[10];
#pragma unroll
        for (int i = 0; i < 10; i++)
            v[i] = u2c(col[(rb + i) * PITCH]);

#pragma unroll
        for (int half = 0; half < 2; half++) {
            Cell w[4];
            tree7(v, w);
#pragma unroll
            for (int q = 0; q < 4; q++) {
                float2 fp = __half22float2(w[q].p);   // (S, S2) pred
                float2 ft = __half22float2(w[q].t);   // (S, S2) tgt
                float mup  = fp.x * NINV;
                float varp = fp.y * NINV - mup * mup;
                float sdp  = fsqrt_fast(varp + EPS);
                float mut  = ft.x * NINV;
                float vart = ft.y * NINV - mut * mut;
                float sdt  = fsqrt_fast(vart + EPS);
                float d  = sdp - sdt;
                float ad = fabsf(d);
                acc += (ad < 1.0f) ? 0.5f * d * d : (ad - 0.5f);
            }
            if (half == 0) {
                // shift window down by 4 rows: rows rb+4..rb+13
#pragma unroll
                for (int i = 0; i < 6; i++) v[i] = v[i + 4];
#pragma unroll
                for (int i = 6; i < 10; i++)
                    v[i] = u2c(col[(rb + 4 + i) * PITCH]);
            }
        }
    }

    // ---- block reduction: warp shuffle + one barrier ----
#pragma unroll
    for (int off = 16; off > 0; off >>= 1)
        acc += __shfl_down_sync(0xffffffffu, acc, off);
    if (lane == 0) s_warp[wid] = acc;
    __syncthreads();                                           // B3

    const int pidx = blockIdx.z * 128 + blockIdx.y * 8 + blockIdx.x;
    if (wid == 0) {
        float a = (lane < 8) ? s_warp[lane] : 0.f;
#pragma unroll
        for (int off = 4; off > 0; off >>= 1)
            a += __shfl_down_sync(0xffffffffu, a, off);
        if (lane == 0) {
            g_partials[pidx] = a;
            __threadfence();
            unsigned int prev = atomicInc(&g_count, NBLK - 1);  // wraps to 0
            s_is_last = (prev == NBLK - 1);
        }
    }
    __syncthreads();                                           // B4

    // ---- last block: final deterministic reduction ----
    if (s_is_last) {
        float a = 0.f;
#pragma unroll
        for (int i = 0; i < NBLK / 256; i++)
            a += g_partials[tid + i * 256];
#pragma unroll
        for (int off = 16; off > 0; off >>= 1)
            a += __shfl_down_sync(0xffffffffu, a, off);
        if (lane == 0) s_warp[wid] = a;
        __syncthreads();
        if (tid == 0) {
            float s = 0.f;
#pragma unroll
            for (int i = 0; i < 8; i++) s += s_warp[i];
            out[0] = s * (1.0f / NPIX);
        }
    }
}

extern "C" void kernel_launch(void* const* d_in, const int* in_sizes, int n_in,
                              void* d_out, int out_size)
{
    const float* pred = (const float*)d_in[0];
    const float* tgt  = (const float*)d_in[1];
    float* out = (float*)d_out;

    dim3 grid(8, 16, 16);   // x tiles (64 wide), y tiles (32 tall), batch
    dim3 block(32, 8);
    dist_loss_main<<<grid, block>>>(pred, tgt, out);
}

// round 15
// speedup vs baseline: 1.0739x; 1.0126x over previous
#include <cuda_runtime.h>
#include <cuda_fp16.h>
#include <math.h>

// DistributionLoss: local 7x7x3 std of two [16,3,512,512] f32 tensors,
// smooth-L1 between std maps, global mean.
//
// R15: R14 base (64x32 tile, warp-local in-place hsum, tree sums, fp16
// cells, RSQ, 4 block barriers) + f32x2 PACKED phase-1 conversion math
// (add/mul/fma.rn.f32x2, 2 pixels per ALU op) + fully unrolled phase-1
// task loop (straight-line LDG batching).

#define TW    64
#define TH    32
#define HALO  3
#define HR    38                  // halo rows  (TH + 6)
#define WC    70                  // halo cols  (TW + 6)
#define PITCH 78                  // smem pitch in 8B cells (even; max addr 77)
#define NINV  (1.0f / 147.0f)
#define EPS   1e-8f
#define HWSZ  (512 * 512)
#define NPIX  (16.0f * 512.0f * 512.0f)
#define NBLK  2048                // 8 x 16 x 16

// Pair-granular swizzle (pairs = 16B units): distinct mod 8 for stride-2.
#define SWP(p) ((p) + ((p) >> 3))
__device__ __forceinline__ int cellAddr(int c) {
    int p = c >> 1;
    return 2 * SWP(p) + (c & 1);
}

__device__ float        g_partials[NBLK];
__device__ unsigned int g_count;   // zero-init; self-resets via atomicInc wrap

struct Cell { __half2 p, t; };     // (s, s2) for pred / tgt

__device__ __forceinline__ Cell mk(unsigned int a, unsigned int b) {
    Cell c;
    c.p = *reinterpret_cast<__half2*>(&a);
    c.t = *reinterpret_cast<__half2*>(&b);
    return c;
}
__device__ __forceinline__ uint2 c2u(Cell c) {
    uint2 v;
    v.x = *reinterpret_cast<unsigned int*>(&c.p);
    v.y = *reinterpret_cast<unsigned int*>(&c.t);
    return v;
}
__device__ __forceinline__ Cell u2c(uint2 v) { return mk(v.x, v.y); }
__device__ __forceinline__ Cell lo4(uint4 u) { return mk(u.x, u.y); }
__device__ __forceinline__ Cell hi4(uint4 u) { return mk(u.z, u.w); }
__device__ __forceinline__ Cell cadd(Cell a, Cell b) {
    Cell r; r.p = __hadd2(a.p, b.p); r.t = __hadd2(a.t, b.t); return r;
}
__device__ __forceinline__ float fsqrt_fast(float x) { return x * rsqrtf(x); }

// ---- packed f32x2 helpers (sm_100+ PTX) ----
typedef unsigned long long u64t;
__device__ __forceinline__ u64t pk2(float lo, float hi) {
    u64t r; asm("mov.b64 %0, {%1, %2};" : "=l"(r) : "f"(lo), "f"(hi)); return r;
}
__device__ __forceinline__ void up2(u64t v, float& lo, float& hi) {
    asm("mov.b64 {%0, %1}, %2;" : "=f"(lo), "=f"(hi) : "l"(v));
}
__device__ __forceinline__ u64t add2x(u64t a, u64t b) {
    u64t r; asm("add.rn.f32x2 %0, %1, %2;" : "=l"(r) : "l"(a), "l"(b)); return r;
}
__device__ __forceinline__ u64t mul2x(u64t a, u64t b) {
    u64t r; asm("mul.rn.f32x2 %0, %1, %2;" : "=l"(r) : "l"(a), "l"(b)); return r;
}
__device__ __forceinline__ u64t fma2x(u64t a, u64t b, u64t c) {
    u64t r; asm("fma.rn.f32x2 %0, %1, %2, %3;" : "=l"(r) : "l"(a), "l"(b), "l"(c)); return r;
}

// Convert a trio of float4 rows (3 channels) into 4 half2(s,s2) cells.
__device__ __forceinline__ void conv4(float4 a0, float4 a1, float4 a2, __half2 h[4]) {
    // xy half
    u64t A0 = pk2(a0.x, a0.y), A1 = pk2(a1.x, a1.y), A2 = pk2(a2.x, a2.y);
    u64t S  = add2x(add2x(A0, A1), A2);
    u64t S2 = fma2x(A2, A2, fma2x(A1, A1, mul2x(A0, A0)));
    float sx, sy, qx, qy;
    up2(S, sx, sy); up2(S2, qx, qy);
    h[0] = __floats2half2_rn(sx, qx);
    h[1] = __floats2half2_rn(sy, qy);
    // zw half
    u64t B0 = pk2(a0.z, a0.w), B1 = pk2(a1.z, a1.w), B2 = pk2(a2.z, a2.w);
    u64t T  = add2x(add2x(B0, B1), B2);
    u64t T2 = fma2x(B2, B2, fma2x(B1, B1, mul2x(B0, B0)));
    float sz, sw, qz, qw;
    up2(T, sz, sw); up2(T2, qz, qw);
    h[2] = __floats2half2_rn(sz, qz);
    h[3] = __floats2half2_rn(sw, qw);
}

// Tree 7-sums over a 10-window: w_j = sum(v[j..j+6]), j=0..3. Depth ~4.
__device__ __forceinline__ void tree7(const Cell v[10], Cell w[4]) {
    Cell p0 = cadd(v[0], v[1]);
    Cell p2 = cadd(v[2], v[3]);
    Cell p4 = cadd(v[4], v[5]);
    Cell p6 = cadd(v[6], v[7]);
    Cell p8 = cadd(v[8], v[9]);
    Cell t  = cadd(p2, p4);
    Cell s1 = cadd(t, p6);
    Cell r  = cadd(p6, p8);
    w[0] = cadd(cadd(p0, t), v[6]);
    w[1] = cadd(v[1], s1);
    w[2] = cadd(s1, v[8]);
    w[3] = cadd(cadd(v[3], p4), r);
}

__global__ __launch_bounds__(256, 6)
void dist_loss_main(const float* __restrict__ pred,
                    const float* __restrict__ tgt,
                    float* __restrict__ out)
{
    __shared__ __align__(16) uint2 s_raw[HR * PITCH];  // cells; hsums in-place
    __shared__ float s_warp[8];
    __shared__ bool  s_is_last;

    const int tid  = threadIdx.y * 32 + threadIdx.x;
    const int lane = threadIdx.x;
    const int wid  = threadIdx.y;
    const int x0   = blockIdx.x * TW;
    const int y0   = blockIdx.y * TH;

    const float* p  = pred + (size_t)blockIdx.z * 3 * HWSZ;
    const float* tg = tgt  + (size_t)blockIdx.z * 3 * HWSZ;

    // ---- Phase 1: 684 tasks = 38 rows x 18 float4 col-groups, unrolled ----
    {
        auto doTask = [&](int task) {
            int r   = task / 18;
            int g   = task - r * 18;
            int gy  = y0 - HALO + r;
            int gx0 = x0 - 4 + 4 * g;
            bool rowok = ((unsigned)gy < 512u);

            __half2 hp[4], ht[4];
            if (rowok && gx0 >= 0 && gx0 <= 508) {
                size_t off = (size_t)gy * 512 + gx0;
                float4 a0 = *(const float4*)(p + off);
                float4 a1 = *(const float4*)(p + HWSZ + off);
                float4 a2 = *(const float4*)(p + 2 * HWSZ + off);
                float4 b0 = *(const float4*)(tg + off);
                float4 b1 = *(const float4*)(tg + HWSZ + off);
                float4 b2 = *(const float4*)(tg + 2 * HWSZ + off);
                conv4(a0, a1, a2, hp);
                conv4(b0, b1, b2, ht);
            } else {
#pragma unroll
                for (int j = 0; j < 4; j++) {
                    int gx = gx0 + j;
                    float v0 = 0.f, v1 = 0.f, v2 = 0.f;
                    float w0 = 0.f, w1 = 0.f, w2 = 0.f;
                    if (rowok && ((unsigned)gx < 512u)) {
                        size_t off = (size_t)gy * 512 + gx;
                        v0 = p[off];  v1 = p[HWSZ + off];  v2 = p[2 * HWSZ + off];
                        w0 = tg[off]; w1 = tg[HWSZ + off]; w2 = tg[2 * HWSZ + off];
                    }
                    hp[j] = __floats2half2_rn(v0 + v1 + v2, v0*v0 + v1*v1 + v2*v2);
                    ht[j] = __floats2half2_rn(w0 + w1 + w2, w0*w0 + w1*w1 + w2*w2);
                }
            }
#pragma unroll
            for (int j = 0; j < 4; j++) {
                int c = 4 * g + j - 1;
                if ((unsigned)c < (unsigned)WC) {
                    Cell cl; cl.p = hp[j]; cl.t = ht[j];
                    s_raw[r * PITCH + cellAddr(c)] = c2u(cl);
                }
            }
        };
        doTask(tid);            // tasks 0..255
        doTask(tid + 256);      // tasks 256..511
        if (tid < HR * 18 - 512)
            doTask(tid + 512);  // tasks 512..683
    }
    __syncthreads();                                           // B1

    // ---- Phase 2: horizontal 7-sum IN PLACE, warp-local rows ----
    {
        const int g2 = lane & 15;
        const int rp = lane >> 4;    // 0 or 1: row within pair
        int pa[5];
#pragma unroll
        for (int i = 0; i < 5; i++) pa[i] = SWP(2 * g2 + i);   // uint4 units

        for (int pairIdx = wid; pairIdx < 19; pairIdx += 8) {
            int r = 2 * pairIdx + rp;                          // 0..37 < HR
            uint4* rp4 = (uint4*)(s_raw + r * PITCH);
            uint4 u0 = rp4[pa[0]];
            uint4 u1 = rp4[pa[1]];
            uint4 u2 = rp4[pa[2]];
            uint4 u3 = rp4[pa[3]];
            uint4 u4v = rp4[pa[4]];
            Cell v[10] = { lo4(u0), hi4(u0), lo4(u1), hi4(u1), lo4(u2),
                           hi4(u2), lo4(u3), hi4(u3), lo4(u4v), hi4(u4v) };
            Cell w[4];
            tree7(v, w);
            uint2 h0 = c2u(w[0]), h1 = c2u(w[1]);
            uint2 h2 = c2u(w[2]), h3 = c2u(w[3]);
            __syncwarp();                                      // loads before stores
            rp4[pa[0]] = make_uint4(h0.x, h0.y, h1.x, h1.y);
            rp4[pa[1]] = make_uint4(h2.x, h2.y, h3.x, h3.y);
            __syncwarp();                                      // stores before next loads
        }
    }
    __syncthreads();                                           // B2

    // ---- Phase 3: vertical tree 7-sums, rolling window, 8 rows/thread ----
    float acc = 0.f;
    {
        const int c3 = tid & 63;     // output col 0..63
        const int rg = tid >> 6;     // 0..3 -> output rows 8rg..8rg+7
        const uint2* col = s_raw + cellAddr(c3);
        const int rb = rg * 8;

        Cell v[10];
#pragma unroll
        for (int i = 0; i < 10; i++)
            v[i] = u2c(col[(rb + i) * PITCH]);

#pragma unroll
        for (int half = 0; half < 2; half++) {
            Cell w[4];
            tree7(v, w);
#pragma unroll
            for (int q = 0; q < 4; q++) {
                float2 fp = __half22float2(w[q].p);
                float2 ft = __half22float2(w[q].t);
                float mup  = fp.x * NINV;
                float varp = fp.y * NINV - mup * mup;
                float sdp  = fsqrt_fast(varp + EPS);
                float mut  = ft.x * NINV;
                float vart = ft.y * NINV - mut * mut;
                float sdt  = fsqrt_fast(vart + EPS);
                float d  = sdp - sdt;
                float ad = fabsf(d);
                acc += (ad < 1.0f) ? 0.5f * d * d : (ad - 0.5f);
            }
            if (half == 0) {
#pragma unroll
                for (int i = 0; i < 6; i++) v[i] = v[i + 4];
#pragma unroll
                for (int i = 6; i < 10; i++)
                    v[i] = u2c(col[(rb + 4 + i) * PITCH]);
            }
        }
    }

    // ---- block reduction: warp shuffle + one barrier ----
#pragma unroll
    for (int off = 16; off > 0; off >>= 1)
        acc += __shfl_down_sync(0xffffffffu, acc, off);
    if (lane == 0) s_warp[wid] = acc;
    __syncthreads();                                           // B3

    const int pidx = blockIdx.z * 128 + blockIdx.y * 8 + blockIdx.x;
    if (wid == 0) {
        float a = (lane < 8) ? s_warp[lane] : 0.f;
#pragma unroll
        for (int off = 4; off > 0; off >>= 1)
            a += __shfl_down_sync(0xffffffffu, a, off);
        if (lane == 0) {
            g_partials[pidx] = a;
            __threadfence();
            unsigned int prev = atomicInc(&g_count, NBLK - 1);  // wraps to 0
            s_is_last = (prev == NBLK - 1);
        }
    }
    __syncthreads();                                           // B4

    // ---- last block: final deterministic reduction ----
    if (s_is_last) {
        float a = 0.f;
#pragma unroll
        for (int i = 0; i < NBLK / 256; i++)
            a += g_partials[tid + i * 256];
#pragma unroll
        for (int off = 16; off > 0; off >>= 1)
            a += __shfl_down_sync(0xffffffffu, a, off);
        if (lane == 0) s_warp[wid] = a;
        __syncthreads();
        if (tid == 0) {
            float s = 0.f;
#pragma unroll
            for (int i = 0; i < 8; i++) s += s_warp[i];
            out[0] = s * (1.0f / NPIX);
        }
    }
}

extern "C" void kernel_launch(void* const* d_in, const int* in_sizes, int n_in,
                              void* d_out, int out_size)
{
    const float* pred = (const float*)d_in[0];
    const float* tgt  = (const float*)d_in[1];
    float* out = (float*)d_out;

    dim3 grid(8, 16, 16);   // x tiles (64 wide), y tiles (32 tall), batch
    dim3 block(32, 8);
    dist_loss_main<<<grid, block>>>(pred, tgt, out);
}